// round 4
// baseline (speedup 1.0000x reference)
#include <cuda_runtime.h>

#define B 32
#define S 2048
#define H 32
#define HKV 8
#define G 4            // H / HKV
#define D 128
#define SPLITS 8
#define CHUNK (S / SPLITS)   // 256
#define NWARP 8
#define SCALE 0.08838834764831845f
#define NEG -1e30f

// split-KV partial scratch (allocation-free: __device__ globals)
__device__ float g_part_o[B * HKV * SPLITS * G * D];
__device__ float g_part_m[B * HKV * SPLITS * G];
__device__ float g_part_l[B * HKV * SPLITS * G];

// 11-shuffle 4-head warp reduction: in lane L, returns the full 32-lane sum of
// head (L & 3)'s partial. sg[g] must hold each lane's partial for head g.
__device__ __forceinline__ float reduce4(float sg[G], int lane)
{
    #pragma unroll
    for (int g = 0; g < G; g++) {
        sg[g] += __shfl_xor_sync(0xffffffffu, sg[g], 1);
        sg[g] += __shfl_xor_sync(0xffffffffu, sg[g], 2);
    }
    const int h = lane & 3;
    float v = (h == 0) ? sg[0] : (h == 1) ? sg[1] : (h == 2) ? sg[2] : sg[3];
    v += __shfl_xor_sync(0xffffffffu, v, 4);
    v += __shfl_xor_sync(0xffffffffu, v, 8);
    v += __shfl_xor_sync(0xffffffffu, v, 16);
    return v;
}

__global__ __launch_bounds__(256) void attn_split_kernel(
    const float* __restrict__ q,
    const float* __restrict__ knew,
    const float* __restrict__ vnew,
    const float* __restrict__ kbuf,
    const float* __restrict__ vbuf,
    const int*   __restrict__ req_to_token,
    const int*   __restrict__ seq_lens,
    const int*   __restrict__ out_cache_loc)
{
    const int bh    = blockIdx.x;           // b * HKV + kh
    const int b     = bh / HKV;
    const int kh    = bh % HKV;
    const int split = blockIdx.y;
    const int tid   = threadIdx.x;
    const int lane  = tid & 31;
    const int warp  = tid >> 5;

    const int seq_len = seq_lens[b];
    const int s0      = split * CHUNK;
    const int nt      = min(seq_len - s0, CHUNK);
    const int pbase   = (bh * SPLITS + split) * G;

    __shared__ float sc[G][CHUNK];          // scores -> probs (4 KB)
    __shared__ float red[NWARP][G * D];     // per-warp V accumulators (16 KB)
    __shared__ float ml_s[2][G];

    if (nt <= 0) {
        for (int i = tid; i < G * D; i += 256) g_part_o[(size_t)pbase * D + i] = 0.f;
        if (tid < G) { g_part_m[pbase + tid] = NEG; g_part_l[pbase + tid] = 0.f; }
        return;
    }

    const int out_loc = out_cache_loc[b];

    // q (scaled) in registers: one float4 per head per lane
    float4 qv[G];
    #pragma unroll
    for (int g = 0; g < G; g++) {
        float4 t = *(const float4*)(q + ((size_t)b * H + kh * G + g) * D + lane * 4);
        qv[g] = make_float4(t.x * SCALE, t.y * SCALE, t.z * SCALE, t.w * SCALE);
    }

    const float* knew_ptr = knew + ((size_t)b * HKV + kh) * D;
    const float* vnew_ptr = vnew + ((size_t)b * HKV + kh) * D;
    const int*   rtab     = req_to_token + (size_t)b * S + s0;

    // ---------- Pass 1: QK^T scores (warp-per-token, 2 tokens in flight) ----------
    int t = warp;
    for (; t + NWARP < nt; t += 2 * NWARP) {
        const int loc0 = rtab[t];
        const int loc1 = rtab[t + NWARP];
        const float* kp0 = (loc0 == out_loc) ? knew_ptr
                                             : (kbuf + ((size_t)loc0 * HKV + kh) * D);
        const float* kp1 = (loc1 == out_loc) ? knew_ptr
                                             : (kbuf + ((size_t)loc1 * HKV + kh) * D);
        float4 k0 = *(const float4*)(kp0 + lane * 4);   // both LDGs issue before use
        float4 k1 = *(const float4*)(kp1 + lane * 4);
        float sg0[G], sg1[G];
        #pragma unroll
        for (int g = 0; g < G; g++) {
            sg0[g] = k0.x * qv[g].x + k0.y * qv[g].y + k0.z * qv[g].z + k0.w * qv[g].w;
            sg1[g] = k1.x * qv[g].x + k1.y * qv[g].y + k1.z * qv[g].z + k1.w * qv[g].w;
        }
        float v0 = reduce4(sg0, lane);
        float v1 = reduce4(sg1, lane);
        if (lane < 4)      sc[lane][t]         = v0;
        else if (lane < 8) sc[lane - 4][t + NWARP] = v1;
    }
    for (; t < nt; t += NWARP) {
        const int loc = rtab[t];
        const float* kp = (loc == out_loc) ? knew_ptr
                                           : (kbuf + ((size_t)loc * HKV + kh) * D);
        float4 k4 = *(const float4*)(kp + lane * 4);
        float sg[G];
        #pragma unroll
        for (int g = 0; g < G; g++)
            sg[g] = k4.x * qv[g].x + k4.y * qv[g].y + k4.z * qv[g].z + k4.w * qv[g].w;
        float v = reduce4(sg, lane);
        if (lane < 4) sc[lane][t] = v;
    }
    __syncthreads();

    // ---------- Pass 2: per-head max & sum-exp (warps 0..3, head = warp) ----------
    if (warp < G) {
        const int g = warp;
        float m = NEG;
        for (int tt = lane; tt < nt; tt += 32) m = fmaxf(m, sc[g][tt]);
        #pragma unroll
        for (int off = 16; off > 0; off >>= 1)
            m = fmaxf(m, __shfl_xor_sync(0xffffffffu, m, off));
        float l = 0.f;
        for (int tt = lane; tt < nt; tt += 32) {
            float e = __expf(sc[g][tt] - m);
            sc[g][tt] = e;
            l += e;
        }
        #pragma unroll
        for (int off = 16; off > 0; off >>= 1)
            l += __shfl_xor_sync(0xffffffffu, l, off);
        if (lane == 0) { ml_s[0][g] = m; ml_s[1][g] = l; }
    }
    __syncthreads();

    // ---------- Pass 3: P @ V (warp-per-token, 2 tokens in flight) ----------
    float4 acc[G];
    #pragma unroll
    for (int g = 0; g < G; g++) acc[g] = make_float4(0.f, 0.f, 0.f, 0.f);

    t = warp;
    for (; t + NWARP < nt; t += 2 * NWARP) {
        const int loc0 = rtab[t];
        const int loc1 = rtab[t + NWARP];
        const float* vp0 = (loc0 == out_loc) ? vnew_ptr
                                             : (vbuf + ((size_t)loc0 * HKV + kh) * D);
        const float* vp1 = (loc1 == out_loc) ? vnew_ptr
                                             : (vbuf + ((size_t)loc1 * HKV + kh) * D);
        float4 v0 = *(const float4*)(vp0 + lane * 4);
        float4 v1 = *(const float4*)(vp1 + lane * 4);
        #pragma unroll
        for (int g = 0; g < G; g++) {
            const float p0 = sc[g][t];
            const float p1 = sc[g][t + NWARP];
            acc[g].x += p0 * v0.x + p1 * v1.x;
            acc[g].y += p0 * v0.y + p1 * v1.y;
            acc[g].z += p0 * v0.z + p1 * v1.z;
            acc[g].w += p0 * v0.w + p1 * v1.w;
        }
    }
    for (; t < nt; t += NWARP) {
        const int loc = rtab[t];
        const float* vp = (loc == out_loc) ? vnew_ptr
                                           : (vbuf + ((size_t)loc * HKV + kh) * D);
        float4 v4 = *(const float4*)(vp + lane * 4);
        #pragma unroll
        for (int g = 0; g < G; g++) {
            const float p = sc[g][t];
            acc[g].x += p * v4.x; acc[g].y += p * v4.y;
            acc[g].z += p * v4.z; acc[g].w += p * v4.w;
        }
    }
    // deterministic cross-warp reduction via smem
    #pragma unroll
    for (int g = 0; g < G; g++)
        *(float4*)&red[warp][g * D + lane * 4] = acc[g];
    __syncthreads();

    for (int i = tid; i < G * D; i += 256) {
        float s = red[0][i];
        #pragma unroll
        for (int w = 1; w < NWARP; w++) s += red[w][i];
        g_part_o[(size_t)pbase * D + i] = s;
    }
    if (tid < G) {
        g_part_m[pbase + tid] = ml_s[0][tid];
        g_part_l[pbase + tid] = ml_s[1][tid];
    }
}

// merge SPLITS partials per (b, kh): one thread per (g, d)
__global__ __launch_bounds__(512) void reduce_kernel(float* __restrict__ out)
{
    const int bh  = blockIdx.x;             // b * HKV + kh
    const int b   = bh / HKV;
    const int kh  = bh % HKV;
    const int tid = threadIdx.x;
    const int g   = tid >> 7;
    const int d   = tid & 127;

    float m = NEG;
    #pragma unroll
    for (int sp = 0; sp < SPLITS; sp++)
        m = fmaxf(m, g_part_m[(bh * SPLITS + sp) * G + g]);

    float L = 0.f, o = 0.f;
    #pragma unroll
    for (int sp = 0; sp < SPLITS; sp++) {
        const int   pi = (bh * SPLITS + sp) * G + g;
        const float w  = __expf(g_part_m[pi] - m);
        L += g_part_l[pi] * w;
        o += g_part_o[(size_t)pi * D + d] * w;
    }
    out[((size_t)b * H + kh * G + g) * D + d] = o / L;
}

extern "C" void kernel_launch(void* const* d_in, const int* in_sizes, int n_in,
                              void* d_out, int out_size)
{
    const float* q        = (const float*)d_in[0];
    const float* knew     = (const float*)d_in[1];
    const float* vnew     = (const float*)d_in[2];
    const float* kbuf     = (const float*)d_in[3];
    const float* vbuf     = (const float*)d_in[4];
    const int*   req2tok  = (const int*)d_in[5];
    const int*   seq_lens = (const int*)d_in[6];
    const int*   out_loc  = (const int*)d_in[7];
    float*       out      = (float*)d_out;

    dim3 grid(B * HKV, SPLITS);
    attn_split_kernel<<<grid, 256>>>(q, knew, vnew, kbuf, vbuf,
                                     req2tok, seq_lens, out_loc);
    reduce_kernel<<<B * HKV, 512>>>(out);
}

// round 5
// speedup vs baseline: 1.2397x; 1.2397x over previous
#include <cuda_runtime.h>

#define B 32
#define S 2048
#define H 32
#define HKV 8
#define G 4            // H / HKV
#define D 128
#define SPLITS 4
#define CHUNK (S / SPLITS)   // 512
#define NWARP 8
#define SCALE 0.08838834764831845f
#define NEG -1e30f

// split-KV partial scratch (allocation-free: __device__ globals)
__device__ float g_part_o[B * HKV * SPLITS * G * D];
__device__ float g_part_m[B * HKV * SPLITS * G];
__device__ float g_part_l[B * HKV * SPLITS * G];

// ncu phase-shift helper: with 4 nodes per replay, skip-5 lands on attn (5 mod 4 == 1)
__global__ void noop_kernel() {}

// 11-shuffle 4-head warp reduction: lane L returns the full 32-lane sum of
// head (L & 3)'s partial. sg[g] holds this lane's partial for head g.
__device__ __forceinline__ float reduce4(float sg[G], int lane)
{
    #pragma unroll
    for (int g = 0; g < G; g++) {
        sg[g] += __shfl_xor_sync(0xffffffffu, sg[g], 1);
        sg[g] += __shfl_xor_sync(0xffffffffu, sg[g], 2);
    }
    const int h = lane & 3;
    float v = (h == 0) ? sg[0] : (h == 1) ? sg[1] : (h == 2) ? sg[2] : sg[3];
    v += __shfl_xor_sync(0xffffffffu, v, 4);
    v += __shfl_xor_sync(0xffffffffu, v, 8);
    v += __shfl_xor_sync(0xffffffffu, v, 16);
    return v;
}

__global__ __launch_bounds__(256) void attn_split_kernel(
    const float* __restrict__ q,
    const float* __restrict__ knew,
    const float* __restrict__ vnew,
    const float* __restrict__ kbuf,
    const float* __restrict__ vbuf,
    const int*   __restrict__ req_to_token,
    const int*   __restrict__ seq_lens,
    const int*   __restrict__ out_cache_loc)
{
    const int bh    = blockIdx.x;           // b * HKV + kh
    const int b     = bh / HKV;
    const int kh    = bh % HKV;
    const int split = blockIdx.y;
    const int tid   = threadIdx.x;
    const int lane  = tid & 31;
    const int warp  = tid >> 5;

    const int seq_len = seq_lens[b];
    const int s0      = split * CHUNK;
    const int nt      = min(seq_len - s0, CHUNK);
    const int pbase   = (bh * SPLITS + split) * G;

    __shared__ float sc[G][CHUNK];          // scores -> probs (8 KB)
    __shared__ float red[NWARP][G * D];     // per-warp V accumulators (16 KB)
    __shared__ float ml_s[2][G];

    if (nt <= 0) {
        for (int i = tid; i < G * D; i += 256) g_part_o[(size_t)pbase * D + i] = 0.f;
        if (tid < G) { g_part_m[pbase + tid] = NEG; g_part_l[pbase + tid] = 0.f; }
        return;
    }

    const int out_loc = out_cache_loc[b];

    // q (scaled) in registers: one float4 per head per lane
    float4 qv[G];
    #pragma unroll
    for (int g = 0; g < G; g++) {
        float4 t = *(const float4*)(q + ((size_t)b * H + kh * G + g) * D + lane * 4);
        qv[g] = make_float4(t.x * SCALE, t.y * SCALE, t.z * SCALE, t.w * SCALE);
    }

    const float* knew_ptr = knew + ((size_t)b * HKV + kh) * D;
    const float* vnew_ptr = vnew + ((size_t)b * HKV + kh) * D;
    const int*   rtab     = req_to_token + (size_t)b * S + s0;

    // ---------- Pass 1: QK^T scores (warp-per-token) ----------
    for (int t = warp; t < nt; t += NWARP) {
        const int loc = rtab[t];
        const float* kp = (loc == out_loc) ? knew_ptr
                                           : (kbuf + ((size_t)loc * HKV + kh) * D);
        float4 k4 = *(const float4*)(kp + lane * 4);
        float sg[G];
        #pragma unroll
        for (int g = 0; g < G; g++)
            sg[g] = k4.x * qv[g].x + k4.y * qv[g].y + k4.z * qv[g].z + k4.w * qv[g].w;
        float v = reduce4(sg, lane);
        if (lane < 4) sc[lane][t] = v;
    }
    __syncthreads();

    // ---------- Pass 2: per-head max & sum-exp (warps 0..3, head = warp) ----------
    if (warp < G) {
        const int g = warp;
        float m = NEG;
        for (int t = lane; t < nt; t += 32) m = fmaxf(m, sc[g][t]);
        #pragma unroll
        for (int off = 16; off > 0; off >>= 1)
            m = fmaxf(m, __shfl_xor_sync(0xffffffffu, m, off));
        float l = 0.f;
        for (int t = lane; t < nt; t += 32) {
            float e = __expf(sc[g][t] - m);
            sc[g][t] = e;
            l += e;
        }
        #pragma unroll
        for (int off = 16; off > 0; off >>= 1)
            l += __shfl_xor_sync(0xffffffffu, l, off);
        if (lane == 0) { ml_s[0][g] = m; ml_s[1][g] = l; }
    }
    __syncthreads();

    // ---------- Pass 3: P @ V (warp-per-token, register accumulate) ----------
    float4 acc[G];
    #pragma unroll
    for (int g = 0; g < G; g++) acc[g] = make_float4(0.f, 0.f, 0.f, 0.f);

    for (int t = warp; t < nt; t += NWARP) {
        const int loc = rtab[t];
        const float* vp = (loc == out_loc) ? vnew_ptr
                                           : (vbuf + ((size_t)loc * HKV + kh) * D);
        float4 v4 = *(const float4*)(vp + lane * 4);
        #pragma unroll
        for (int g = 0; g < G; g++) {
            const float p = sc[g][t];      // smem broadcast
            acc[g].x += p * v4.x; acc[g].y += p * v4.y;
            acc[g].z += p * v4.z; acc[g].w += p * v4.w;
        }
    }
    // deterministic cross-warp reduction via smem
    #pragma unroll
    for (int g = 0; g < G; g++)
        *(float4*)&red[warp][g * D + lane * 4] = acc[g];
    __syncthreads();

    for (int i = tid; i < G * D; i += 256) {
        float s = red[0][i];
        #pragma unroll
        for (int w = 1; w < NWARP; w++) s += red[w][i];
        g_part_o[(size_t)pbase * D + i] = s;
    }
    if (tid < G) {
        g_part_m[pbase + tid] = ml_s[0][tid];
        g_part_l[pbase + tid] = ml_s[1][tid];
    }
}

// merge SPLITS partials per (b, kh): one thread per (g, d)
__global__ __launch_bounds__(512) void reduce_kernel(float* __restrict__ out)
{
    const int bh  = blockIdx.x;             // b * HKV + kh
    const int b   = bh / HKV;
    const int kh  = bh % HKV;
    const int tid = threadIdx.x;
    const int g   = tid >> 7;
    const int d   = tid & 127;

    float m = NEG;
    #pragma unroll
    for (int sp = 0; sp < SPLITS; sp++)
        m = fmaxf(m, g_part_m[(bh * SPLITS + sp) * G + g]);

    float L = 0.f, o = 0.f;
    #pragma unroll
    for (int sp = 0; sp < SPLITS; sp++) {
        const int   pi = (bh * SPLITS + sp) * G + g;
        const float w  = __expf(g_part_m[pi] - m);
        L += g_part_l[pi] * w;
        o += g_part_o[(size_t)pi * D + d] * w;
    }
    out[((size_t)b * H + kh * G + g) * D + d] = o / L;
}

extern "C" void kernel_launch(void* const* d_in, const int* in_sizes, int n_in,
                              void* d_out, int out_size)
{
    const float* q        = (const float*)d_in[0];
    const float* knew     = (const float*)d_in[1];
    const float* vnew     = (const float*)d_in[2];
    const float* kbuf     = (const float*)d_in[3];
    const float* vbuf     = (const float*)d_in[4];
    const int*   req2tok  = (const int*)d_in[5];
    const int*   seq_lens = (const int*)d_in[6];
    const int*   out_loc  = (const int*)d_in[7];
    float*       out      = (float*)d_out;

    // 4 launches per replay -> ncu's skip-5 capture (5 mod 4 == 1) lands on attn
    noop_kernel<<<1, 1>>>();
    dim3 grid(B * HKV, SPLITS);
    attn_split_kernel<<<grid, 256>>>(q, knew, vnew, kbuf, vbuf,
                                     req2tok, seq_lens, out_loc);
    reduce_kernel<<<B * HKV, 512>>>(out);
    noop_kernel<<<1, 1>>>();
}

// round 6
// speedup vs baseline: 1.2689x; 1.0236x over previous
#include <cuda_runtime.h>

#define B 32
#define S 2048
#define H 32
#define HKV 8
#define G 4            // H / HKV
#define D 128
#define SPLITS 4
#define CHUNK (S / SPLITS)   // 512
#define NWARP 8
#define SCALE 0.08838834764831845f
#define NEG -1e30f

// split-KV partial scratch (allocation-free: __device__ globals)
__device__ float g_part_o[B * HKV * SPLITS * G * D];
__device__ float g_part_m[B * HKV * SPLITS * G];
__device__ float g_part_l[B * HKV * SPLITS * G];
__device__ int   g_cnt[B * HKV];   // zero-init; each use returns it to zero

// 11-shuffle 4-head warp reduction: lane L returns the full 32-lane sum of
// head (L & 3)'s partial. sg[g] holds this lane's partial for head g.
__device__ __forceinline__ float reduce4(float sg[G], int lane)
{
    #pragma unroll
    for (int g = 0; g < G; g++) {
        sg[g] += __shfl_xor_sync(0xffffffffu, sg[g], 1);
        sg[g] += __shfl_xor_sync(0xffffffffu, sg[g], 2);
    }
    const int h = lane & 3;
    float v = (h == 0) ? sg[0] : (h == 1) ? sg[1] : (h == 2) ? sg[2] : sg[3];
    v += __shfl_xor_sync(0xffffffffu, v, 4);
    v += __shfl_xor_sync(0xffffffffu, v, 8);
    v += __shfl_xor_sync(0xffffffffu, v, 16);
    return v;
}

__global__ __launch_bounds__(256) void attn_fused_kernel(
    const float* __restrict__ q,
    const float* __restrict__ knew,
    const float* __restrict__ vnew,
    const float* __restrict__ kbuf,
    const float* __restrict__ vbuf,
    const int*   __restrict__ req_to_token,
    const int*   __restrict__ seq_lens,
    const int*   __restrict__ out_cache_loc,
    float*       __restrict__ out)
{
    const int bh    = blockIdx.x;           // b * HKV + kh
    const int b     = bh / HKV;
    const int kh    = bh % HKV;
    const int split = blockIdx.y;
    const int tid   = threadIdx.x;
    const int lane  = tid & 31;
    const int warp  = tid >> 5;

    const int seq_len = seq_lens[b];
    const int s0      = split * CHUNK;
    const int nt      = min(seq_len - s0, CHUNK);
    const int pbase   = (bh * SPLITS + split) * G;

    __shared__ float sc[G][CHUNK];          // scores -> probs (8 KB)
    __shared__ float red[NWARP][G * D];     // per-warp V accumulators (16 KB)
    __shared__ float ml_s[2][G];
    __shared__ int   is_last;

    if (nt > 0) {
        const int out_loc = out_cache_loc[b];

        // q (scaled) in registers: one float4 per head per lane
        float4 qv[G];
        #pragma unroll
        for (int g = 0; g < G; g++) {
            float4 t = *(const float4*)(q + ((size_t)b * H + kh * G + g) * D + lane * 4);
            qv[g] = make_float4(t.x * SCALE, t.y * SCALE, t.z * SCALE, t.w * SCALE);
        }

        const float* knew_ptr = knew + ((size_t)b * HKV + kh) * D;
        const float* vnew_ptr = vnew + ((size_t)b * HKV + kh) * D;
        const int*   rtab     = req_to_token + (size_t)b * S + s0;

        // ---------- Pass 1: QK^T scores (warp-per-token) ----------
        for (int t = warp; t < nt; t += NWARP) {
            const int loc = rtab[t];
            const float* kp = (loc == out_loc) ? knew_ptr
                                               : (kbuf + ((size_t)loc * HKV + kh) * D);
            float4 k4 = *(const float4*)(kp + lane * 4);
            float sg[G];
            #pragma unroll
            for (int g = 0; g < G; g++)
                sg[g] = k4.x * qv[g].x + k4.y * qv[g].y + k4.z * qv[g].z + k4.w * qv[g].w;
            float v = reduce4(sg, lane);
            if (lane < 4) sc[lane][t] = v;
        }
        __syncthreads();

        // ---------- Pass 2: per-head max & sum-exp (warps 0..3, head = warp) ----------
        if (warp < G) {
            const int g = warp;
            float m = NEG;
            for (int t = lane; t < nt; t += 32) m = fmaxf(m, sc[g][t]);
            #pragma unroll
            for (int off = 16; off > 0; off >>= 1)
                m = fmaxf(m, __shfl_xor_sync(0xffffffffu, m, off));
            float l = 0.f;
            for (int t = lane; t < nt; t += 32) {
                float e = __expf(sc[g][t] - m);
                sc[g][t] = e;
                l += e;
            }
            #pragma unroll
            for (int off = 16; off > 0; off >>= 1)
                l += __shfl_xor_sync(0xffffffffu, l, off);
            if (lane == 0) { ml_s[0][g] = m; ml_s[1][g] = l; }
        }
        __syncthreads();

        // ---------- Pass 3: P @ V (warp-per-token, register accumulate) ----------
        float4 acc[G];
        #pragma unroll
        for (int g = 0; g < G; g++) acc[g] = make_float4(0.f, 0.f, 0.f, 0.f);

        for (int t = warp; t < nt; t += NWARP) {
            const int loc = rtab[t];
            const float* vp = (loc == out_loc) ? vnew_ptr
                                               : (vbuf + ((size_t)loc * HKV + kh) * D);
            float4 v4 = *(const float4*)(vp + lane * 4);
            #pragma unroll
            for (int g = 0; g < G; g++) {
                const float p = sc[g][t];      // smem broadcast
                acc[g].x += p * v4.x; acc[g].y += p * v4.y;
                acc[g].z += p * v4.z; acc[g].w += p * v4.w;
            }
        }
        // deterministic cross-warp reduction via smem
        #pragma unroll
        for (int g = 0; g < G; g++)
            *(float4*)&red[warp][g * D + lane * 4] = acc[g];
        __syncthreads();

        for (int i = tid; i < G * D; i += 256) {
            float s = red[0][i];
            #pragma unroll
            for (int w = 1; w < NWARP; w++) s += red[w][i];
            g_part_o[(size_t)pbase * D + i] = s;
        }
        if (tid < G) {
            g_part_m[pbase + tid] = ml_s[0][tid];
            g_part_l[pbase + tid] = ml_s[1][tid];
        }
    } else {
        for (int i = tid; i < G * D; i += 256) g_part_o[(size_t)pbase * D + i] = 0.f;
        if (tid < G) { g_part_m[pbase + tid] = NEG; g_part_l[pbase + tid] = 0.f; }
    }

    // ---------- completion count: last CTA of this bh merges the splits ----------
    __threadfence();
    if (tid == 0) {
        int old = atomicAdd(&g_cnt[bh], 1);
        is_last = (old == SPLITS - 1) ? 1 : 0;
    }
    __syncthreads();
    if (!is_last) return;

    // merge (reads are ordered after all writers' fences via the atomic chain)
    for (int i = tid; i < G * D; i += 256) {
        const int g = i >> 7;
        const int d = i & 127;
        float m = NEG;
        #pragma unroll
        for (int sp = 0; sp < SPLITS; sp++)
            m = fmaxf(m, g_part_m[(bh * SPLITS + sp) * G + g]);
        float L = 0.f, o = 0.f;
        #pragma unroll
        for (int sp = 0; sp < SPLITS; sp++) {
            const int   pi = (bh * SPLITS + sp) * G + g;
            const float w  = __expf(g_part_m[pi] - m);
            L += g_part_l[pi] * w;
            o += g_part_o[(size_t)pi * D + d] * w;
        }
        out[((size_t)b * H + kh * G + g) * D + d] = o / L;
    }
    if (tid == 0) g_cnt[bh] = 0;   // reset for next replay (deterministic)
}

extern "C" void kernel_launch(void* const* d_in, const int* in_sizes, int n_in,
                              void* d_out, int out_size)
{
    const float* q        = (const float*)d_in[0];
    const float* knew     = (const float*)d_in[1];
    const float* vnew     = (const float*)d_in[2];
    const float* kbuf     = (const float*)d_in[3];
    const float* vbuf     = (const float*)d_in[4];
    const int*   req2tok  = (const int*)d_in[5];
    const int*   seq_lens = (const int*)d_in[6];
    const int*   out_loc  = (const int*)d_in[7];
    float*       out      = (float*)d_out;

    dim3 grid(B * HKV, SPLITS);
    attn_fused_kernel<<<grid, 256>>>(q, knew, vnew, kbuf, vbuf,
                                     req2tok, seq_lens, out_loc, out);
}

// round 8
// speedup vs baseline: 1.4185x; 1.1179x over previous
#include <cuda_runtime.h>

#define B 32
#define S 2048
#define H 32
#define HKV 8
#define G 4            // H / HKV
#define D 128
#define SPLITS 4
#define CHUNK (S / SPLITS)   // 512
#define NWARP 8
#define SCALE 0.08838834764831845f
#define NEG -1e30f

// split-KV partial scratch (allocation-free: __device__ globals)
__device__ float g_part_o[B * HKV * SPLITS * G * D];
__device__ float g_part_m[B * HKV * SPLITS * G];
__device__ float g_part_l[B * HKV * SPLITS * G];
__device__ int   g_cnt[B * HKV];   // zero-init; every replay returns it to zero

// 11-shuffle 4-head warp reduction: lane L returns the full 32-lane sum of
// head (L & 3)'s partial. sg[g] holds this lane's partial for head g.
__device__ __forceinline__ float reduce4(float sg[G], int lane)
{
    #pragma unroll
    for (int g = 0; g < G; g++) {
        sg[g] += __shfl_xor_sync(0xffffffffu, sg[g], 1);
        sg[g] += __shfl_xor_sync(0xffffffffu, sg[g], 2);
    }
    const int h = lane & 3;
    float v = (h == 0) ? sg[0] : (h == 1) ? sg[1] : (h == 2) ? sg[2] : sg[3];
    v += __shfl_xor_sync(0xffffffffu, v, 4);
    v += __shfl_xor_sync(0xffffffffu, v, 8);
    v += __shfl_xor_sync(0xffffffffu, v, 16);
    return v;
}

__global__ __launch_bounds__(256, 6) void attn_fused_kernel(
    const float* __restrict__ q,
    const float* __restrict__ knew,
    const float* __restrict__ vnew,
    const float* __restrict__ kbuf,
    const float* __restrict__ vbuf,
    const int*   __restrict__ req_to_token,
    const int*   __restrict__ seq_lens,
    const int*   __restrict__ out_cache_loc,
    float*       __restrict__ out)
{
    const int bh    = blockIdx.x;           // b * HKV + kh
    const int b     = bh / HKV;
    const int kh    = bh % HKV;
    const int split = blockIdx.y;
    const int tid   = threadIdx.x;
    const int lane  = tid & 31;
    const int warp  = tid >> 5;

    const int seq_len = seq_lens[b];
    const int s0      = split * CHUNK;
    const int nt      = min(seq_len - s0, CHUNK);
    const int pbase   = (bh * SPLITS + split) * G;

    // 16 KB shared buffer, time-multiplexed:
    //   phase A (pass 1-3): sc[G][CHUNK] scores->probs (first 8 KB)
    //   phase B (epilogue): red[NWARP][G*D] cross-warp combine (all 16 KB)
    __shared__ float sbuf[NWARP * G * D];
    __shared__ float ml_s[2][G];
    __shared__ int   is_last;
    float (*sc)[CHUNK] = (float (*)[CHUNK])sbuf;

    if (nt > 0) {
        const int out_loc = out_cache_loc[b];

        // q (scaled) in registers: one float4 per head per lane
        float4 qv[G];
        #pragma unroll
        for (int g = 0; g < G; g++) {
            float4 t = *(const float4*)(q + ((size_t)b * H + kh * G + g) * D + lane * 4);
            qv[g] = make_float4(t.x * SCALE, t.y * SCALE, t.z * SCALE, t.w * SCALE);
        }

        const float* knew_ptr = knew + ((size_t)b * HKV + kh) * D;
        const float* vnew_ptr = vnew + ((size_t)b * HKV + kh) * D;
        const int*   rtab     = req_to_token + (size_t)b * S + s0;

        // ---------- Pass 1: QK^T (warp-per-token, 2-deep LDG pipeline) ----------
        {
            int t = warp;
            float4 kn;
            if (t < nt) {
                const int loc = rtab[t];
                const float* kp = (loc == out_loc) ? knew_ptr
                                                   : (kbuf + ((size_t)loc * HKV + kh) * D);
                kn = *(const float4*)(kp + lane * 4);
            }
            for (; t < nt; t += NWARP) {
                const float4 kc = kn;
                const int tn = t + NWARP;
                if (tn < nt) {                          // issue next LDG before compute
                    const int loc = rtab[tn];
                    const float* kp = (loc == out_loc) ? knew_ptr
                                                       : (kbuf + ((size_t)loc * HKV + kh) * D);
                    kn = *(const float4*)(kp + lane * 4);
                }
                float sg[G];
                #pragma unroll
                for (int g = 0; g < G; g++)
                    sg[g] = kc.x * qv[g].x + kc.y * qv[g].y + kc.z * qv[g].z + kc.w * qv[g].w;
                float v = reduce4(sg, lane);
                if (lane < 4) sc[lane][t] = v;
            }
        }
        __syncthreads();

        // ---------- Pass 2: per-head max & sum-exp (warps 0..3, head = warp) ----------
        if (warp < G) {
            const int g = warp;
            float m = NEG;
            for (int t = lane; t < nt; t += 32) m = fmaxf(m, sc[g][t]);
            #pragma unroll
            for (int off = 16; off > 0; off >>= 1)
                m = fmaxf(m, __shfl_xor_sync(0xffffffffu, m, off));
            float l = 0.f;
            for (int t = lane; t < nt; t += 32) {
                float e = __expf(sc[g][t] - m);
                sc[g][t] = e;
                l += e;
            }
            #pragma unroll
            for (int off = 16; off > 0; off >>= 1)
                l += __shfl_xor_sync(0xffffffffu, l, off);
            if (lane == 0) { ml_s[0][g] = m; ml_s[1][g] = l; }
        }
        __syncthreads();

        // ---------- Pass 3: P @ V (warp-per-token, 2-deep LDG pipeline) ----------
        float4 acc[G];
        #pragma unroll
        for (int g = 0; g < G; g++) acc[g] = make_float4(0.f, 0.f, 0.f, 0.f);

        {
            int t = warp;
            float4 vn;
            if (t < nt) {
                const int loc = rtab[t];
                const float* vp = (loc == out_loc) ? vnew_ptr
                                                   : (vbuf + ((size_t)loc * HKV + kh) * D);
                vn = *(const float4*)(vp + lane * 4);
            }
            for (; t < nt; t += NWARP) {
                const float4 vc = vn;
                const int tn = t + NWARP;
                if (tn < nt) {                          // issue next LDG before compute
                    const int loc = rtab[tn];
                    const float* vp = (loc == out_loc) ? vnew_ptr
                                                       : (vbuf + ((size_t)loc * HKV + kh) * D);
                    vn = *(const float4*)(vp + lane * 4);
                }
                #pragma unroll
                for (int g = 0; g < G; g++) {
                    const float p = sc[g][t];      // smem broadcast
                    acc[g].x += p * vc.x; acc[g].y += p * vc.y;
                    acc[g].z += p * vc.z; acc[g].w += p * vc.w;
                }
            }
        }
        __syncthreads();                 // all sc reads done: sbuf can be reused
        // deterministic cross-warp reduction via smem (red aliases sc region)
        float* red = sbuf;               // red[NWARP][G*D]
        #pragma unroll
        for (int g = 0; g < G; g++)
            *(float4*)&red[(warp * G + g) * D + lane * 4] = acc[g];
        __syncthreads();

        for (int i = tid; i < G * D; i += 256) {
            float s = red[i];
            #pragma unroll
            for (int w = 1; w < NWARP; w++) s += red[w * G * D + i];
            g_part_o[(size_t)pbase * D + i] = s;
        }
        if (tid < G) {
            g_part_m[pbase + tid] = ml_s[0][tid];
            g_part_l[pbase + tid] = ml_s[1][tid];
        }
    } else {
        for (int i = tid; i < G * D; i += 256) g_part_o[(size_t)pbase * D + i] = 0.f;
        if (tid < G) { g_part_m[pbase + tid] = NEG; g_part_l[pbase + tid] = 0.f; }
    }

    // ---------- completion count: last CTA of this bh merges the splits ----------
    __threadfence();
    if (tid == 0) {
        int old = atomicAdd(&g_cnt[bh], 1);
        is_last = (old == SPLITS - 1) ? 1 : 0;
    }
    __syncthreads();
    if (!is_last) return;

    for (int i = tid; i < G * D; i += 256) {
        const int g = i >> 7;
        const int d = i & 127;
        float m = NEG;
        #pragma unroll
        for (int sp = 0; sp < SPLITS; sp++)
            m = fmaxf(m, g_part_m[(bh * SPLITS + sp) * G + g]);
        float L = 0.f, o = 0.f;
        #pragma unroll
        for (int sp = 0; sp < SPLITS; sp++) {
            const int   pi = (bh * SPLITS + sp) * G + g;
            const float w  = __expf(g_part_m[pi] - m);
            L += g_part_l[pi] * w;
            o += g_part_o[(size_t)pi * D + d] * w;
        }
        out[((size_t)b * H + kh * G + g) * D + d] = o / L;
    }
    if (tid == 0) g_cnt[bh] = 0;   // reset for next replay (deterministic)
}

extern "C" void kernel_launch(void* const* d_in, const int* in_sizes, int n_in,
                              void* d_out, int out_size)
{
    const float* q        = (const float*)d_in[0];
    const float* knew     = (const float*)d_in[1];
    const float* vnew     = (const float*)d_in[2];
    const float* kbuf     = (const float*)d_in[3];
    const float* vbuf     = (const float*)d_in[4];
    const int*   req2tok  = (const int*)d_in[5];
    const int*   seq_lens = (const int*)d_in[6];
    const int*   out_loc  = (const int*)d_in[7];
    float*       out      = (float*)d_out;

    dim3 grid(B * HKV, SPLITS);
    attn_fused_kernel<<<grid, 256>>>(q, knew, vnew, kbuf, vbuf,
                                     req2tok, seq_lens, out_loc, out);
}